// round 3
// baseline (speedup 1.0000x reference)
#include <cuda_runtime.h>
#include <math.h>

#define BB     2
#define SS     2048
#define DMODEL 1024
#define HQ     32
#define HKV    8
#define HD     32

// ---------------- scratch (no allocs allowed) ----------------
__device__ float g_q [BB*HQ *SS*HD];   // [b][h][s][d]
__device__ float g_k [BB*HKV*SS*HD];
__device__ float g_v [BB*HKV*SS*HD];
__device__ float g_ao[BB*SS*DMODEL];   // attention out, [b][s][h*HD+d]

// ---------------- GEMM config ----------------
#define GBM 128
#define GBN 128
#define GBK 16
#define GTM 8
#define GTN 8

// C[m,n] = sum_k A[m,k] * W[n,k];  fused Q/K/V with scatter epilogue
__global__ __launch_bounds__(256) void gemm_qkv(
    const float* __restrict__ A,
    const float* __restrict__ Wq,
    const float* __restrict__ Wk,
    const float* __restrict__ Wv)
{
    __shared__ float As[GBK][GBM];
    __shared__ float Bs[GBK][GBN];

    const int m0 = blockIdx.y * GBM;
    const int n0 = blockIdx.x * GBN;

    const float* W; int wn0; float* dst; int H;
    if (n0 < 1024)      { W = Wq; wn0 = n0;        dst = g_q; H = HQ;  }
    else if (n0 < 1280) { W = Wk; wn0 = n0 - 1024; dst = g_k; H = HKV; }
    else                { W = Wv; wn0 = n0 - 1280; dst = g_v; H = HKV; }

    const int tid = threadIdx.x;
    const int tx  = tid & 15;
    const int ty  = tid >> 4;

    float acc[GTM][GTN];
    #pragma unroll
    for (int i = 0; i < GTM; i++)
        #pragma unroll
        for (int j = 0; j < GTN; j++) acc[i][j] = 0.f;

    for (int k0 = 0; k0 < DMODEL; k0 += GBK) {
        #pragma unroll
        for (int it = 0; it < 2; it++) {
            int idx = tid + it * 256;
            int row = idx >> 2;
            int c4  = idx & 3;
            float4 va = *(const float4*)&A[(m0 + row) * DMODEL + k0 + c4 * 4];
            As[c4*4+0][row] = va.x; As[c4*4+1][row] = va.y;
            As[c4*4+2][row] = va.z; As[c4*4+3][row] = va.w;
            float4 vb = *(const float4*)&W[(wn0 + row) * DMODEL + k0 + c4 * 4];
            Bs[c4*4+0][row] = vb.x; Bs[c4*4+1][row] = vb.y;
            Bs[c4*4+2][row] = vb.z; Bs[c4*4+3][row] = vb.w;
        }
        __syncthreads();
        #pragma unroll
        for (int k = 0; k < GBK; k++) {
            float4 a0 = *(const float4*)&As[k][ty * GTM];
            float4 a1 = *(const float4*)&As[k][ty * GTM + 4];
            float4 b0 = *(const float4*)&Bs[k][tx * GTN];
            float4 b1 = *(const float4*)&Bs[k][tx * GTN + 4];
            float ar[8] = {a0.x,a0.y,a0.z,a0.w,a1.x,a1.y,a1.z,a1.w};
            float br[8] = {b0.x,b0.y,b0.z,b0.w,b1.x,b1.y,b1.z,b1.w};
            #pragma unroll
            for (int i = 0; i < GTM; i++)
                #pragma unroll
                for (int j = 0; j < GTN; j++)
                    acc[i][j] += ar[i] * br[j];
        }
        __syncthreads();
    }

    #pragma unroll
    for (int i = 0; i < GTM; i++) {
        int m = m0 + ty * GTM + i;
        int b = m >> 11;
        int s = m & (SS - 1);
        #pragma unroll
        for (int j = 0; j < GTN; j++) {
            int nl = wn0 + tx * GTN + j;
            int h  = nl >> 5;
            int d  = nl & 31;
            dst[((b * H + h) * SS + s) * HD + d] = acc[i][j];
        }
    }
}

// output projection: C = g_ao @ Wo^T (plain row-major out)
__global__ __launch_bounds__(256) void gemm_out(
    const float* __restrict__ W, float* __restrict__ C)
{
    __shared__ float As[GBK][GBM];
    __shared__ float Bs[GBK][GBN];

    const int m0 = blockIdx.y * GBM;
    const int n0 = blockIdx.x * GBN;
    const int tid = threadIdx.x;
    const int tx  = tid & 15;
    const int ty  = tid >> 4;

    float acc[GTM][GTN];
    #pragma unroll
    for (int i = 0; i < GTM; i++)
        #pragma unroll
        for (int j = 0; j < GTN; j++) acc[i][j] = 0.f;

    for (int k0 = 0; k0 < DMODEL; k0 += GBK) {
        #pragma unroll
        for (int it = 0; it < 2; it++) {
            int idx = tid + it * 256;
            int row = idx >> 2;
            int c4  = idx & 3;
            float4 va = *(const float4*)&g_ao[(m0 + row) * DMODEL + k0 + c4 * 4];
            As[c4*4+0][row] = va.x; As[c4*4+1][row] = va.y;
            As[c4*4+2][row] = va.z; As[c4*4+3][row] = va.w;
            float4 vb = *(const float4*)&W[(n0 + row) * DMODEL + k0 + c4 * 4];
            Bs[c4*4+0][row] = vb.x; Bs[c4*4+1][row] = vb.y;
            Bs[c4*4+2][row] = vb.z; Bs[c4*4+3][row] = vb.w;
        }
        __syncthreads();
        #pragma unroll
        for (int k = 0; k < GBK; k++) {
            float4 a0 = *(const float4*)&As[k][ty * GTM];
            float4 a1 = *(const float4*)&As[k][ty * GTM + 4];
            float4 b0 = *(const float4*)&Bs[k][tx * GTN];
            float4 b1 = *(const float4*)&Bs[k][tx * GTN + 4];
            float ar[8] = {a0.x,a0.y,a0.z,a0.w,a1.x,a1.y,a1.z,a1.w};
            float br[8] = {b0.x,b0.y,b0.z,b0.w,b1.x,b1.y,b1.z,b1.w};
            #pragma unroll
            for (int i = 0; i < GTM; i++)
                #pragma unroll
                for (int j = 0; j < GTN; j++)
                    acc[i][j] += ar[i] * br[j];
        }
        __syncthreads();
    }

    #pragma unroll
    for (int i = 0; i < GTM; i++) {
        int m = m0 + ty * GTM + i;
        #pragma unroll
        for (int j = 0; j < GTN; j++)
            C[m * DMODEL + n0 + tx * GTN + j] = acc[i][j];
    }
}

// ---------------- RoPE over g_q and g_k ----------------
__global__ void rope_kernel() {
    const int NQROWS = BB * HQ * SS;
    const int TOT    = (NQROWS + BB * HKV * SS) * 16;
    int gid = blockIdx.x * blockDim.x + threadIdx.x;
    if (gid >= TOT) return;
    int row = gid >> 4;
    int i   = gid & 15;
    float* base = (row < NQROWS) ? (g_q + row * HD)
                                 : (g_k + (row - NQROWS) * HD);
    int s = row & (SS - 1);
    // inv_freq = 10000^(-i/16)
    float inv_freq = expf(-(float)i * (9.210340371976184f / 16.0f));
    float ang = (float)s * inv_freq;
    float c, sn;
    sincosf(ang, &sn, &c);
    float x1 = base[i];
    float x2 = base[i + 16];
    base[i]      = x1 * c - x2 * sn;
    base[i + 16] = x2 * c + x1 * sn;
}

// ---------------- causal GQA flash attention ----------------
// one thread = one query row; K/V tiles of 64 keys in SMEM (broadcast reads)
__global__ __launch_bounds__(128) void attention_kernel(const int* __restrict__ mask) {
    const int b   = blockIdx.z;
    const int h   = blockIdx.y;
    const int q0  = blockIdx.x * 128;
    const int tid = threadIdx.x;
    const int r   = q0 + tid;
    const int kvh = h >> 2;   // GROUP = 4
    const float scale = 0.17677669529663687f; // 1/sqrt(32)

    __shared__ float4 Ks[64][8];
    __shared__ float4 Vs[64][8];
    __shared__ int smask[64];

    const float* qp = g_q + ((b * HQ + h) * SS + r) * HD;
    float4 qv[8];
    #pragma unroll
    for (int c = 0; c < 8; c++) {
        qv[c] = ((const float4*)qp)[c];
        qv[c].x *= scale; qv[c].y *= scale; qv[c].z *= scale; qv[c].w *= scale;
    }

    const float* kbase = g_k + (b * HKV + kvh) * SS * HD;
    const float* vbase = g_v + (b * HKV + kvh) * SS * HD;
    const int*   mbase = mask + b * SS;

    float4 acc[8];
    #pragma unroll
    for (int c = 0; c < 8; c++) acc[c] = make_float4(0.f, 0.f, 0.f, 0.f);
    float mrun = -1e30f, l = 0.f;

    const int jmax = q0 + 127;
    for (int j0 = 0; j0 <= jmax; j0 += 64) {
        for (int t = tid; t < 512; t += 128) {
            int row = t >> 3, c = t & 7;
            Ks[row][c] = ((const float4*)(kbase + (j0 + row) * HD))[c];
            Vs[row][c] = ((const float4*)(vbase + (j0 + row) * HD))[c];
        }
        if (tid < 64) smask[tid] = mbase[j0 + tid];
        __syncthreads();

        #pragma unroll 1
        for (int jc = 0; jc < 64; jc += 16) {
            float sc[16];
            float tmax = -1e30f;
            #pragma unroll
            for (int j = 0; j < 16; j++) {
                int jj = jc + j;
                float4 dp = make_float4(0.f, 0.f, 0.f, 0.f);
                #pragma unroll
                for (int c = 0; c < 8; c++) {
                    float4 kv = Ks[jj][c];
                    dp.x += qv[c].x * kv.x; dp.y += qv[c].y * kv.y;
                    dp.z += qv[c].z * kv.z; dp.w += qv[c].w * kv.w;
                }
                float dot = (dp.x + dp.y) + (dp.z + dp.w);
                bool ok = (j0 + jj <= r) && (smask[jj] != 0);
                sc[j] = ok ? dot : -1e9f;
                tmax = fmaxf(tmax, sc[j]);
            }
            float newm = fmaxf(mrun, tmax);
            float corr = __expf(mrun - newm);
            l *= corr;
            #pragma unroll
            for (int c = 0; c < 8; c++) {
                acc[c].x *= corr; acc[c].y *= corr;
                acc[c].z *= corr; acc[c].w *= corr;
            }
            #pragma unroll
            for (int j = 0; j < 16; j++) {
                float p = __expf(sc[j] - newm);
                l += p;
                int jj = jc + j;
                #pragma unroll
                for (int c = 0; c < 8; c++) {
                    float4 vv = Vs[jj][c];
                    acc[c].x += p * vv.x; acc[c].y += p * vv.y;
                    acc[c].z += p * vv.z; acc[c].w += p * vv.w;
                }
            }
            mrun = newm;
        }
        __syncthreads();
    }

    float inv = 1.0f / l;
    float* op = g_ao + (b * SS + r) * DMODEL + h * HD;
    #pragma unroll
    for (int c = 0; c < 8; c++) {
        float4 o = acc[c];
        o.x *= inv; o.y *= inv; o.z *= inv; o.w *= inv;
        ((float4*)op)[c] = o;
    }
}

// ---------------- launch ----------------
extern "C" void kernel_launch(void* const* d_in, const int* in_sizes, int n_in,
                              void* d_out, int out_size) {
    const float* hs  = (const float*)d_in[0];
    const int*   msk = (const int*)  d_in[1];
    const float* Wq  = (const float*)d_in[2];
    const float* Wk  = (const float*)d_in[3];
    const float* Wv  = (const float*)d_in[4];
    const float* Wo  = (const float*)d_in[5];
    float* out = (float*)d_out;

    // QKV projections (N = 1024 + 256 + 256 = 1536)
    gemm_qkv<<<dim3(1536 / GBN, (BB * SS) / GBM), 256>>>(hs, Wq, Wk, Wv);

    // RoPE on q and k
    int ropeThreads = (BB * HQ * SS + BB * HKV * SS) * 16;
    rope_kernel<<<(ropeThreads + 255) / 256, 256>>>();

    // causal GQA attention
    attention_kernel<<<dim3(SS / 128, HQ, BB), 128>>>(msk);

    // output projection
    gemm_out<<<dim3(DMODEL / GBN, (BB * SS) / GBM), 256>>>(Wo, out);
}

// round 5
// speedup vs baseline: 1.1080x; 1.1080x over previous
#include <cuda_runtime.h>
#include <math.h>

#define BB     2
#define SS     2048
#define DMODEL 1024
#define HQ     32
#define HKV    8
#define HD     32

// ---------------- scratch (no allocs allowed) ----------------
__device__ float g_q [BB*HQ *SS*HD];   // [b][h][s][d]
__device__ float g_k [BB*HKV*SS*HD];
__device__ float g_v [BB*HKV*SS*HD];
__device__ float g_ao[BB*SS*DMODEL];   // attention out, [b][s][h*HD+d]

// ---------------- GEMM config ----------------
#define GBM 128
#define GBN 128
#define GBK 16
#define NT  (DMODEL / GBK)

// stash one 128x16 A tile + 128x16 B tile (from 4 prefetch regs) into stage `bf`
#define STASH(bf)                                                              \
    do {                                                                       \
        As[bf][lc+0][lrow]    = ra0.x; As[bf][lc+1][lrow]    = ra0.y;          \
        As[bf][lc+2][lrow]    = ra0.z; As[bf][lc+3][lrow]    = ra0.w;          \
        As[bf][lc+0][lrow+64] = ra1.x; As[bf][lc+1][lrow+64] = ra1.y;          \
        As[bf][lc+2][lrow+64] = ra1.z; As[bf][lc+3][lrow+64] = ra1.w;          \
        Bs[bf][lc+0][lrow]    = rb0.x; Bs[bf][lc+1][lrow]    = rb0.y;          \
        Bs[bf][lc+2][lrow]    = rb0.z; Bs[bf][lc+3][lrow]    = rb0.w;          \
        Bs[bf][lc+0][lrow+64] = rb1.x; Bs[bf][lc+1][lrow+64] = rb1.y;          \
        Bs[bf][lc+2][lrow+64] = rb1.z; Bs[bf][lc+3][lrow+64] = rb1.w;          \
    } while (0)

#define GEMM_MAINLOOP()                                                        \
    float4 ra0 = *(const float4*)pa0;                                          \
    float4 ra1 = *(const float4*)pa1;                                          \
    float4 rb0 = *(const float4*)pb0;                                          \
    float4 rb1 = *(const float4*)pb1;                                          \
    STASH(0);                                                                  \
    __syncthreads();                                                           \
    int buf = 0;                                                               \
    for (int t = 0; t < NT; t++) {                                             \
        if (t + 1 < NT) {                                                      \
            pa0 += GBK; pa1 += GBK; pb0 += GBK; pb1 += GBK;                    \
            ra0 = *(const float4*)pa0; ra1 = *(const float4*)pa1;              \
            rb0 = *(const float4*)pb0; rb1 = *(const float4*)pb1;              \
        }                                                                      \
        _Pragma("unroll")                                                      \
        for (int k = 0; k < GBK; k++) {                                        \
            float4 a0 = *(const float4*)&As[buf][k][ty * 8];                   \
            float4 a1 = *(const float4*)&As[buf][k][ty * 8 + 4];               \
            float4 b0 = *(const float4*)&Bs[buf][k][tx * 8];                   \
            float4 b1 = *(const float4*)&Bs[buf][k][tx * 8 + 4];               \
            float ar[8] = {a0.x,a0.y,a0.z,a0.w,a1.x,a1.y,a1.z,a1.w};           \
            float br[8] = {b0.x,b0.y,b0.z,b0.w,b1.x,b1.y,b1.z,b1.w};           \
            _Pragma("unroll")                                                  \
            for (int i = 0; i < 8; i++)                                        \
                _Pragma("unroll")                                              \
                for (int j = 0; j < 8; j++)                                    \
                    acc[i][j] += ar[i] * br[j];                                \
        }                                                                      \
        if (t + 1 < NT) {                                                      \
            STASH(buf ^ 1);                                                    \
            __syncthreads();                                                   \
            buf ^= 1;                                                          \
        }                                                                      \
    }

// fused Q/K/V projection with scatter epilogue
__global__ __launch_bounds__(256, 2) void gemm_qkv(
    const float* __restrict__ A,
    const float* __restrict__ Wq,
    const float* __restrict__ Wk,
    const float* __restrict__ Wv)
{
    __shared__ float As[2][GBK][GBM];
    __shared__ float Bs[2][GBK][GBN];

    const int m0 = blockIdx.y * GBM;
    const int n0 = blockIdx.x * GBN;

    const float* W; int wn0; float* dst; int H;
    if (n0 < 1024)      { W = Wq; wn0 = n0;        dst = g_q; H = HQ;  }
    else if (n0 < 1280) { W = Wk; wn0 = n0 - 1024; dst = g_k; H = HKV; }
    else                { W = Wv; wn0 = n0 - 1280; dst = g_v; H = HKV; }

    const int tid  = threadIdx.x;
    const int tx   = tid & 15;
    const int ty   = tid >> 4;
    const int lrow = tid >> 2;
    const int lc   = (tid & 3) * 4;

    const float* pa0 = A + (m0 + lrow)      * DMODEL + lc;
    const float* pa1 = A + (m0 + lrow + 64) * DMODEL + lc;
    const float* pb0 = W + (wn0 + lrow)      * DMODEL + lc;
    const float* pb1 = W + (wn0 + lrow + 64) * DMODEL + lc;

    float acc[8][8];
    #pragma unroll
    for (int i = 0; i < 8; i++)
        #pragma unroll
        for (int j = 0; j < 8; j++) acc[i][j] = 0.f;

    GEMM_MAINLOOP();

    #pragma unroll
    for (int i = 0; i < 8; i++) {
        int m = m0 + ty * 8 + i;
        int b = m >> 11;
        int s = m & (SS - 1);
        #pragma unroll
        for (int j = 0; j < 8; j++) {
            int nl = wn0 + tx * 8 + j;
            int h  = nl >> 5;
            int d  = nl & 31;
            dst[((b * H + h) * SS + s) * HD + d] = acc[i][j];
        }
    }
}

// output projection: C = g_ao @ Wo^T
__global__ __launch_bounds__(256, 2) void gemm_out(
    const float* __restrict__ W, float* __restrict__ C)
{
    __shared__ float As[2][GBK][GBM];
    __shared__ float Bs[2][GBK][GBN];

    const int m0 = blockIdx.y * GBM;
    const int n0 = blockIdx.x * GBN;

    const int tid  = threadIdx.x;
    const int tx   = tid & 15;
    const int ty   = tid >> 4;
    const int lrow = tid >> 2;
    const int lc   = (tid & 3) * 4;

    const float* pa0 = g_ao + (m0 + lrow)      * DMODEL + lc;
    const float* pa1 = g_ao + (m0 + lrow + 64) * DMODEL + lc;
    const float* pb0 = W + (n0 + lrow)      * DMODEL + lc;
    const float* pb1 = W + (n0 + lrow + 64) * DMODEL + lc;

    float acc[8][8];
    #pragma unroll
    for (int i = 0; i < 8; i++)
        #pragma unroll
        for (int j = 0; j < 8; j++) acc[i][j] = 0.f;

    GEMM_MAINLOOP();

    #pragma unroll
    for (int i = 0; i < 8; i++) {
        int m = m0 + ty * 8 + i;
        #pragma unroll
        for (int j = 0; j < 8; j++)
            C[m * DMODEL + n0 + tx * 8 + j] = acc[i][j];
    }
}

// ---------------- RoPE over g_q and g_k ----------------
__global__ void rope_kernel() {
    const int NQROWS = BB * HQ * SS;
    const int TOT    = (NQROWS + BB * HKV * SS) * 16;
    int gid = blockIdx.x * blockDim.x + threadIdx.x;
    if (gid >= TOT) return;
    int row = gid >> 4;
    int i   = gid & 15;
    float* base = (row < NQROWS) ? (g_q + row * HD)
                                 : (g_k + (row - NQROWS) * HD);
    int s = row & (SS - 1);
    float inv_freq = expf(-(float)i * (9.210340371976184f / 16.0f));
    float ang = (float)s * inv_freq;
    float c, sn;
    sincosf(ang, &sn, &c);
    float x1 = base[i];
    float x2 = base[i + 16];
    base[i]      = x1 * c - x2 * sn;
    base[i + 16] = x2 * c + x1 * sn;
}

// ---------------- causal GQA flash attention ----------------
// one thread = one query row for TWO adjacent Q heads (same KV head).
// K/V float4 LDS amortized over 2 dot/acc streams -> ~2x FMA density.
__global__ __launch_bounds__(128, 1) void attention_kernel(const int* __restrict__ mask) {
    const int b   = blockIdx.z;
    const int h0  = blockIdx.y * 2;          // heads h0, h0+1 share kv head
    const int q0  = blockIdx.x * 128;
    const int tid = threadIdx.x;
    const int r   = q0 + tid;
    const int kvh = h0 >> 2;                 // GROUP = 4
    const float scale = 0.17677669529663687f; // 1/sqrt(32)

    __shared__ float4 Ks[64][8];
    __shared__ float4 Vs[64][8];
    __shared__ int smask[64];

    const float* qp0 = g_q + ((b * HQ + h0    ) * SS + r) * HD;
    const float* qp1 = g_q + ((b * HQ + h0 + 1) * SS + r) * HD;
    float4 qa[8], qb[8];
    #pragma unroll
    for (int c = 0; c < 8; c++) {
        qa[c] = ((const float4*)qp0)[c];
        qa[c].x *= scale; qa[c].y *= scale; qa[c].z *= scale; qa[c].w *= scale;
        qb[c] = ((const float4*)qp1)[c];
        qb[c].x *= scale; qb[c].y *= scale; qb[c].z *= scale; qb[c].w *= scale;
    }

    const float* kbase = g_k + (b * HKV + kvh) * SS * HD;
    const float* vbase = g_v + (b * HKV + kvh) * SS * HD;
    const int*   mbase = mask + b * SS;

    float4 acc0[8], acc1[8];
    #pragma unroll
    for (int c = 0; c < 8; c++) {
        acc0[c] = make_float4(0.f, 0.f, 0.f, 0.f);
        acc1[c] = make_float4(0.f, 0.f, 0.f, 0.f);
    }
    float m0 = -1e30f, l0 = 0.f;
    float m1 = -1e30f, l1 = 0.f;

    const int jmax = q0 + 127;
    for (int j0 = 0; j0 <= jmax; j0 += 64) {
        for (int t = tid; t < 512; t += 128) {
            int row = t >> 3, c = t & 7;
            Ks[row][c] = ((const float4*)(kbase + (j0 + row) * HD))[c];
            Vs[row][c] = ((const float4*)(vbase + (j0 + row) * HD))[c];
        }
        if (tid < 64) smask[tid] = mbase[j0 + tid];
        __syncthreads();

        #pragma unroll 1
        for (int jc = 0; jc < 64; jc += 8) {
            float s0[8], s1[8];
            float t0 = -1e30f, t1 = -1e30f;
            #pragma unroll
            for (int j = 0; j < 8; j++) {
                int jj = jc + j;
                float4 d0 = make_float4(0.f, 0.f, 0.f, 0.f);
                float4 d1 = make_float4(0.f, 0.f, 0.f, 0.f);
                #pragma unroll
                for (int c = 0; c < 8; c++) {
                    float4 kv = Ks[jj][c];
                    d0.x += qa[c].x * kv.x; d0.y += qa[c].y * kv.y;
                    d0.z += qa[c].z * kv.z; d0.w += qa[c].w * kv.w;
                    d1.x += qb[c].x * kv.x; d1.y += qb[c].y * kv.y;
                    d1.z += qb[c].z * kv.z; d1.w += qb[c].w * kv.w;
                }
                float dot0 = (d0.x + d0.y) + (d0.z + d0.w);
                float dot1 = (d1.x + d1.y) + (d1.z + d1.w);
                bool ok = (j0 + jj <= r) && (smask[jj] != 0);
                s0[j] = ok ? dot0 : -1e9f;  t0 = fmaxf(t0, s0[j]);
                s1[j] = ok ? dot1 : -1e9f;  t1 = fmaxf(t1, s1[j]);
            }
            // conditional rescale: max update is rare (~ln(S) times per row)
            if (t0 > m0) {
                float nm = t0;
                float corr = __expf(m0 - nm);
                l0 *= corr;
                #pragma unroll
                for (int c = 0; c < 8; c++) {
                    acc0[c].x *= corr; acc0[c].y *= corr;
                    acc0[c].z *= corr; acc0[c].w *= corr;
                }
                m0 = nm;
            }
            if (t1 > m1) {
                float nm = t1;
                float corr = __expf(m1 - nm);
                l1 *= corr;
                #pragma unroll
                for (int c = 0; c < 8; c++) {
                    acc1[c].x *= corr; acc1[c].y *= corr;
                    acc1[c].z *= corr; acc1[c].w *= corr;
                }
                m1 = nm;
            }
            #pragma unroll
            for (int j = 0; j < 8; j++) {
                float p0 = __expf(s0[j] - m0);  l0 += p0;
                float p1 = __expf(s1[j] - m1);  l1 += p1;
                int jj = jc + j;
                #pragma unroll
                for (int c = 0; c < 8; c++) {
                    float4 vv = Vs[jj][c];
                    acc0[c].x += p0 * vv.x; acc0[c].y += p0 * vv.y;
                    acc0[c].z += p0 * vv.z; acc0[c].w += p0 * vv.w;
                    acc1[c].x += p1 * vv.x; acc1[c].y += p1 * vv.y;
                    acc1[c].z += p1 * vv.z; acc1[c].w += p1 * vv.w;
                }
            }
        }
        __syncthreads();
    }

    float i0 = 1.0f / l0;
    float i1 = 1.0f / l1;
    float* op = g_ao + (b * SS + r) * DMODEL + h0 * HD;  // heads contiguous
    #pragma unroll
    for (int c = 0; c < 8; c++) {
        float4 o = acc0[c];
        o.x *= i0; o.y *= i0; o.z *= i0; o.w *= i0;
        ((float4*)op)[c] = o;
        float4 o1 = acc1[c];
        o1.x *= i1; o1.y *= i1; o1.z *= i1; o1.w *= i1;
        ((float4*)(op + HD))[c] = o1;
    }
}

// ---------------- launch ----------------
extern "C" void kernel_launch(void* const* d_in, const int* in_sizes, int n_in,
                              void* d_out, int out_size) {
    const float* hs  = (const float*)d_in[0];
    const int*   msk = (const int*)  d_in[1];
    const float* Wq  = (const float*)d_in[2];
    const float* Wk  = (const float*)d_in[3];
    const float* Wv  = (const float*)d_in[4];
    const float* Wo  = (const float*)d_in[5];
    float* out = (float*)d_out;

    gemm_qkv<<<dim3(1536 / GBN, (BB * SS) / GBM), 256>>>(hs, Wq, Wk, Wv);

    int ropeThreads = (BB * HQ * SS + BB * HKV * SS) * 16;
    rope_kernel<<<(ropeThreads + 255) / 256, 256>>>();

    attention_kernel<<<dim3(SS / 128, HQ / 2, BB), 128>>>(msk);

    gemm_out<<<dim3(DMODEL / GBN, (BB * SS) / GBM), 256>>>(Wo, out);
}